// round 2
// baseline (speedup 1.0000x reference)
#include <cuda_runtime.h>
#include <cuda_bf16.h>
#include <math.h>

// HashedInterpolator: 3-D hash-grid trilinear interpolation.
// position: [B, 3] f32 in [0,1);  hash_table: [524288, 4] f32;  out: [B, 4] f32.
//
// R2 changes vs R1:
//  - table gathers via __ldcg (L2-only, no L1 allocate): kills L1 fill wavefronts
//    on the ~97%-miss random gather stream.
//  - positions staged through shared memory with coalesced float4 loads
//    (9 -> 3 L1 wavefronts per warp for the position read).
//  - output via __stcs streaming store.

#define HG_ENTRIES 524288
#define HG_MASK    (HG_ENTRIES - 1)
#define HG_P1      19349663u
#define HG_P2      83492791u

#define TPB 256

__global__ __launch_bounds__(TPB) void hashed_interp_kernel(
    const float* __restrict__ pos,
    const float4* __restrict__ table,
    float4* __restrict__ out,
    int batch)
{
    __shared__ float sp[3 * TPB];

    int t = threadIdx.x;
    int base = blockIdx.x * TPB;          // first point of this block

    // Stage this block's positions (3*TPB floats = 192 float4s) coalesced.
    {
        int nfloats = 3 * (batch - base);     // floats available for this block
        if (nfloats > 3 * TPB) nfloats = 3 * TPB;
        const float4* src = (const float4*)(pos + 3 * base);  // 3072B-aligned blocks
        int nvec = nfloats >> 2;
        if (t < nvec) ((float4*)sp)[t] = src[t];
        // tail floats (only possible on the last, partial block)
        int rem = nfloats & 3;
        if (t < rem) sp[(nvec << 2) + t] = pos[3 * base + (nvec << 2) + t];
    }
    __syncthreads();

    int i = base + t;
    if (i >= batch) return;

    float px = sp[3 * t + 0];
    float py = sp[3 * t + 1];
    float pz = sp[3 * t + 2];

    int lx = (int)floorf(px * 512.0f);
    int ly = (int)floorf(py * 512.0f);
    int lz = (int)floorf(pz * 512.0f);

    const float inv = 1.0f / 512.0f;   // exact
    // bit 0 -> (pos - ll)/size ; bit 1 -> (ul - pos)/size ; size == 1/512 exactly.
    float wx0 = (px - (float)lx * inv) * 512.0f;
    float wx1 = ((float)(lx + 1) * inv - px) * 512.0f;
    float wy0 = (py - (float)ly * inv) * 512.0f;
    float wy1 = ((float)(ly + 1) * inv - py) * 512.0f;
    float wz0 = (pz - (float)lz * inv) * 512.0f;
    float wz1 = ((float)(lz + 1) * inv - pz) * 512.0f;

    unsigned hx0 = (unsigned)lx;
    unsigned hx1 = (unsigned)(lx + 1);
    unsigned hy0 = (unsigned)ly * HG_P1;
    unsigned hy1 = (unsigned)(ly + 1) * HG_P1;
    unsigned hz0 = (unsigned)lz * HG_P2;
    unsigned hz1 = (unsigned)(lz + 1) * HG_P2;

    unsigned i000 = (hx0 ^ hy0 ^ hz0) & HG_MASK;
    unsigned i001 = (hx0 ^ hy0 ^ hz1) & HG_MASK;
    unsigned i010 = (hx0 ^ hy1 ^ hz0) & HG_MASK;
    unsigned i011 = (hx0 ^ hy1 ^ hz1) & HG_MASK;
    unsigned i100 = (hx1 ^ hy0 ^ hz0) & HG_MASK;
    unsigned i101 = (hx1 ^ hy0 ^ hz1) & HG_MASK;
    unsigned i110 = (hx1 ^ hy1 ^ hz0) & HG_MASK;
    unsigned i111 = (hx1 ^ hy1 ^ hz1) & HG_MASK;

    // All 8 independent gathers up front (MLP=8), L2-only (no L1 allocate).
    float4 v000 = __ldcg(&table[i000]);
    float4 v001 = __ldcg(&table[i001]);
    float4 v010 = __ldcg(&table[i010]);
    float4 v011 = __ldcg(&table[i011]);
    float4 v100 = __ldcg(&table[i100]);
    float4 v101 = __ldcg(&table[i101]);
    float4 v110 = __ldcg(&table[i110]);
    float4 v111 = __ldcg(&table[i111]);

    float w000 = wx0 * wy0 * wz0;
    float w001 = wx0 * wy0 * wz1;
    float w010 = wx0 * wy1 * wz0;
    float w011 = wx0 * wy1 * wz1;
    float w100 = wx1 * wy0 * wz0;
    float w101 = wx1 * wy0 * wz1;
    float w110 = wx1 * wy1 * wz0;
    float w111 = wx1 * wy1 * wz1;

    float4 acc;
    acc.x = v000.x * w000;
    acc.y = v000.y * w000;
    acc.z = v000.z * w000;
    acc.w = v000.w * w000;

    acc.x = fmaf(v001.x, w001, acc.x);
    acc.y = fmaf(v001.y, w001, acc.y);
    acc.z = fmaf(v001.z, w001, acc.z);
    acc.w = fmaf(v001.w, w001, acc.w);

    acc.x = fmaf(v010.x, w010, acc.x);
    acc.y = fmaf(v010.y, w010, acc.y);
    acc.z = fmaf(v010.z, w010, acc.z);
    acc.w = fmaf(v010.w, w010, acc.w);

    acc.x = fmaf(v011.x, w011, acc.x);
    acc.y = fmaf(v011.y, w011, acc.y);
    acc.z = fmaf(v011.z, w011, acc.z);
    acc.w = fmaf(v011.w, w011, acc.w);

    acc.x = fmaf(v100.x, w100, acc.x);
    acc.y = fmaf(v100.y, w100, acc.y);
    acc.z = fmaf(v100.z, w100, acc.z);
    acc.w = fmaf(v100.w, w100, acc.w);

    acc.x = fmaf(v101.x, w101, acc.x);
    acc.y = fmaf(v101.y, w101, acc.y);
    acc.z = fmaf(v101.z, w101, acc.z);
    acc.w = fmaf(v101.w, w101, acc.w);

    acc.x = fmaf(v110.x, w110, acc.x);
    acc.y = fmaf(v110.y, w110, acc.y);
    acc.z = fmaf(v110.z, w110, acc.z);
    acc.w = fmaf(v110.w, w110, acc.w);

    acc.x = fmaf(v111.x, w111, acc.x);
    acc.y = fmaf(v111.y, w111, acc.y);
    acc.z = fmaf(v111.z, w111, acc.z);
    acc.w = fmaf(v111.w, w111, acc.w);

    __stcs(&out[i], acc);
}

extern "C" void kernel_launch(void* const* d_in, const int* in_sizes, int n_in,
                              void* d_out, int out_size)
{
    const float* pos = (const float*)d_in[0];
    const float4* table = (const float4*)d_in[1];
    float4* out = (float4*)d_out;
    int batch = in_sizes[0] / 3;

    int blocks = (batch + TPB - 1) / TPB;
    hashed_interp_kernel<<<blocks, TPB>>>(pos, table, out, batch);
}

// round 3
// speedup vs baseline: 1.4392x; 1.4392x over previous
#include <cuda_runtime.h>
#include <cuda_bf16.h>
#include <math.h>

// HashedInterpolator: 3-D hash-grid trilinear interpolation.
// position: [B,3] f32 in [0,1);  hash_table: [524288,4] f32;  out: [B,4] f32.
//
// R3: lane-pair x-merge. hash uses prime 1 on dim x, so for even lx the
// corners (lx,y,z) and (lx+1,y,z) hash to consecutive table rows (h, h^1)
// -> same 128B line. Two lanes of the same LDG instruction load the two
// x-corners, so L1 coalesces them into ONE wavefront for even lx (50% of
// points): 8 -> 6 expected wavefronts per point.

#define HG_ENTRIES 524288
#define HG_MASK    (HG_ENTRIES - 1)
#define HG_P1      19349663u
#define HG_P2      83492791u

#define TPB 256
#define PPB (TPB / 2)          // points per block (2 lanes per point)

__global__ __launch_bounds__(TPB) void hashed_interp_kernel(
    const float* __restrict__ pos,
    const float4* __restrict__ table,
    float4* __restrict__ out,
    int batch)
{
    __shared__ float sp[3 * PPB];

    int t = threadIdx.x;
    int base = blockIdx.x * PPB;          // first point of this block

    // Stage this block's positions (3*PPB floats = 96 float4s) coalesced.
    {
        int nfloats = 3 * (batch - base);
        if (nfloats > 3 * PPB) nfloats = 3 * PPB;
        const float4* src = (const float4*)(pos + 3 * base);  // 1536B-aligned
        int nvec = nfloats >> 2;
        if (t < nvec) ((float4*)sp)[t] = src[t];
        int rem = nfloats & 3;
        if (t < rem) sp[(nvec << 2) + t] = pos[3 * base + (nvec << 2) + t];
    }
    __syncthreads();

    int p    = t >> 1;          // point slot within block
    int xbit = t & 1;           // which x-corner this lane owns
    int i    = base + p;
    if (i >= batch) return;

    float px = sp[3 * p + 0];
    float py = sp[3 * p + 1];
    float pz = sp[3 * p + 2];

    int lx = (int)floorf(px * 512.0f);
    int ly = (int)floorf(py * 512.0f);
    int lz = (int)floorf(pz * 512.0f);

    const float inv = 1.0f / 512.0f;   // exact
    // bit 0 -> (pos - ll)/size ; bit 1 -> (ul - pos)/size ; size == 1/512.
    float wx0 = (px - (float)lx * inv) * 512.0f;
    float wx1 = ((float)(lx + 1) * inv - px) * 512.0f;
    float wy0 = (py - (float)ly * inv) * 512.0f;
    float wy1 = ((float)(ly + 1) * inv - py) * 512.0f;
    float wz0 = (pz - (float)lz * inv) * 512.0f;
    float wz1 = ((float)(lz + 1) * inv - pz) * 512.0f;

    float wx = xbit ? wx1 : wx0;

    unsigned hx  = (unsigned)(lx + xbit);
    unsigned hy0 = (unsigned)ly * HG_P1;
    unsigned hy1 = (unsigned)(ly + 1) * HG_P1;
    unsigned hz0 = (unsigned)lz * HG_P2;
    unsigned hz1 = (unsigned)(lz + 1) * HG_P2;

    unsigned i00 = (hx ^ hy0 ^ hz0) & HG_MASK;
    unsigned i01 = (hx ^ hy0 ^ hz1) & HG_MASK;
    unsigned i10 = (hx ^ hy1 ^ hz0) & HG_MASK;
    unsigned i11 = (hx ^ hy1 ^ hz1) & HG_MASK;

    // 4 gathers per lane, all independent (MLP=4 per lane, 8 per point).
    // Lane pair (2i, 2i+1) issues the same instruction for the same (y,z)
    // combo -> their two addresses share a 128B line when lx is even.
    float4 v00 = __ldcg(&table[i00]);
    float4 v01 = __ldcg(&table[i01]);
    float4 v10 = __ldcg(&table[i10]);
    float4 v11 = __ldcg(&table[i11]);

    float w00 = wx * wy0 * wz0;
    float w01 = wx * wy0 * wz1;
    float w10 = wx * wy1 * wz0;
    float w11 = wx * wy1 * wz1;

    float4 acc;
    acc.x = v00.x * w00;
    acc.y = v00.y * w00;
    acc.z = v00.z * w00;
    acc.w = v00.w * w00;

    acc.x = fmaf(v01.x, w01, acc.x);
    acc.y = fmaf(v01.y, w01, acc.y);
    acc.z = fmaf(v01.z, w01, acc.z);
    acc.w = fmaf(v01.w, w01, acc.w);

    acc.x = fmaf(v10.x, w10, acc.x);
    acc.y = fmaf(v10.y, w10, acc.y);
    acc.z = fmaf(v10.z, w10, acc.z);
    acc.w = fmaf(v10.w, w10, acc.w);

    acc.x = fmaf(v11.x, w11, acc.x);
    acc.y = fmaf(v11.y, w11, acc.y);
    acc.z = fmaf(v11.z, w11, acc.z);
    acc.w = fmaf(v11.w, w11, acc.w);

    // Pair reduction: lane 2i += lane 2i+1.
    acc.x += __shfl_xor_sync(0xffffffffu, acc.x, 1);
    acc.y += __shfl_xor_sync(0xffffffffu, acc.y, 1);
    acc.z += __shfl_xor_sync(0xffffffffu, acc.z, 1);
    acc.w += __shfl_xor_sync(0xffffffffu, acc.w, 1);

    if (xbit == 0)
        __stcs(&out[i], acc);
}

extern "C" void kernel_launch(void* const* d_in, const int* in_sizes, int n_in,
                              void* d_out, int out_size)
{
    const float* pos = (const float*)d_in[0];
    const float4* table = (const float4*)d_in[1];
    float4* out = (float4*)d_out;
    int batch = in_sizes[0] / 3;

    int blocks = (batch + PPB - 1) / PPB;
    hashed_interp_kernel<<<blocks, TPB>>>(pos, table, out, batch);
}